// round 17
// baseline (speedup 1.0000x reference)
#include <cuda_runtime.h>
#include <math.h>

// ---------------------------------------------------------------------------
// Problem constants (shapes fixed by setup_inputs)
// ---------------------------------------------------------------------------
#define B_SZ   2
#define C_SZ   128
#define S_SZ   262144          // 64*64*64 voxels per (b,c)
#define NPAIR  (B_SZ * C_SZ)   // 256
#define NCHUNK 8
#define POOL_ITEMS (NPAIR * NCHUNK)    // 2048
#define GBASES 8               // GRID_SIZE + SPLINE_ORDER = 5 + 3

#define TILE_VOX 128                   // voxels per fused tile
#define TILE_V4  32                    // float4 lanes per tile
#define NTILES  (B_SZ * (S_SZ / TILE_VOX))  // 4096

// Scratch (no device allocation allowed)
__device__ float g_psum[POOL_ITEMS];
__device__ float g_pmax[POOL_ITEMS];
__device__ float g_att[NPAIR];     // sigmoid channel attention per (b,c)
__device__ float g_wc[NPAIR];      // att * conv_w  per (b,c)
__device__ unsigned g_bar_count = 0;
__device__ unsigned g_bar_epoch = 0;   // monotonic across graph replays
__device__ float g_sink;

// ---------------------------------------------------------------------------
// Grid-wide barrier. Safe because the grid is sized to the queried occupancy
// (all blocks co-resident). Epoch is monotonic -> consistent across replays.
// ---------------------------------------------------------------------------
__device__ __forceinline__ void grid_barrier() {
    __threadfence();                   // all threads: flush my global writes
    __syncthreads();
    if (threadIdx.x == 0) {
        const unsigned e = *(volatile unsigned*)&g_bar_epoch;
        __threadfence();               // order epoch read before arrival
        const unsigned old = atomicAdd(&g_bar_count, 1u);
        if (old == gridDim.x - 1u) {
            atomicExch(&g_bar_count, 0u);
            __threadfence();
            atomicAdd(&g_bar_epoch, 1u);   // release
        } else {
            while (*(volatile unsigned*)&g_bar_epoch == e) __nanosleep(64);
        }
        __threadfence();
    }
    __syncthreads();
}

// ---------------------------------------------------------------------------
// Cox-de Boor B-spline bases, k=3, grid = arange(-3,9)*0.4 - 1  (12 knots).
// Uniform grid -> FDIV replaced by multiply with compile-time reciprocals.
// ---------------------------------------------------------------------------
__device__ __forceinline__ void bspline8(float x, float* __restrict__ out) {
    float grid[12];
#pragma unroll
    for (int i = 0; i < 12; i++) grid[i] = (float)(i - 3) * 0.4f - 1.0f;
    float b[11];
#pragma unroll
    for (int j = 0; j < 11; j++)
        b[j] = (x >= grid[j] && x < grid[j + 1]) ? 1.0f : 0.0f;
    const float inv[3] = {2.5f, 1.25f, 1.0f / 1.2f};
#pragma unroll
    for (int j = 1; j <= 3; j++) {
        const float r = inv[j - 1];
#pragma unroll
        for (int m = 0; m < 11; m++) {
            if (m < 11 - j) {
                b[m] = (x - grid[m]) * r * b[m]
                     + (grid[m + j + 1] - x) * r * b[m + 1];
            }
        }
    }
#pragma unroll
    for (int g = 0; g < GBASES; g++) out[g] = b[g];
}

__device__ __forceinline__ float siluf(float v) { return v * (1.0f / (1.0f + __expf(-v))); }
__device__ __forceinline__ float sigmoidf_(float v) { return 1.0f / (1.0f + __expf(-v)); }

// ---------------------------------------------------------------------------
// THE kernel: persistent, grid = occupancy * numSMs blocks x 512 threads.
//   Phase A: pooling (2048 items strided over blocks)  [+ weight prefetch]
//   Phase B: channel MLP on blocks 0,1 (one per batch)
//   Phase C: fused spatial pass, ~14 tiles per block (proven R7 body)
// ---------------------------------------------------------------------------
__global__ void __launch_bounds__(512, 2) mega_kernel(
    const float* __restrict__ x,
    const float* __restrict__ ck1b,   // [8,128]
    const float* __restrict__ ck1s,   // [8,128,8]
    const float* __restrict__ ck2b,   // [128,8]
    const float* __restrict__ ck2s,   // [128,8,8]
    const float* __restrict__ convw,  // [128]
    const float* __restrict__ skb,    // [1]
    const float* __restrict__ sks,    // [8]
    float* __restrict__ out)
{
    __shared__ float ss[16], sm2[16];
    __shared__ float s_silu[256];
    __shared__ float s_bas[256][GBASES];
    __shared__ float s_h1silu[16];
    __shared__ float s_h1bas[16][GBASES];
    __shared__ float s_out[256];
    __shared__ float att_s[NPAIR], wc_s[NPAIR];
    __shared__ float4 wred[16][TILE_V4];
    __shared__ __align__(16) float satts[TILE_VOX];

    const int tid  = threadIdx.x;
    const int wrp  = tid >> 5;
    const int lane = tid & 31;
    const unsigned nb = gridDim.x;
    const float4* xp = (const float4*)x;
    float4* op = (float4*)out;

    // ---- Phase A: pooling (block 2 also pre-touches MLP weights into L2) --
    if (blockIdx.x == 2) {
        float acc = 0.0f;
        for (int i = tid; i < 8192; i += 512)
            acc += __ldcg(&ck1s[i]) + __ldcg(&ck2s[i]);
        for (int i = tid; i < 1024; i += 512)
            acc += __ldcg(&ck1b[i]) + __ldcg(&ck2b[i]);
        if (tid < 128) acc += __ldcg(&convw[tid]);
        if (acc == 123456789.0f) g_sink = acc;   // keep alive; never true
    }

    for (unsigned item = blockIdx.x; item < POOL_ITEMS; item += nb) {
        const int pair  = item >> 3;
        const int chunk = item & 7;
        const float4* p = xp + ((size_t)pair << 16) + (size_t)chunk * 8192;

        float s = 0.0f, m = -3.4e38f;
#pragma unroll
        for (int r = 0; r < 2; r++) {
            float4 v[8];
#pragma unroll
            for (int it = 0; it < 8; it++)
                v[it] = __ldcs(&p[r * 4096 + it * 512 + tid]);
#pragma unroll
            for (int it = 0; it < 8; it++) {
                s += (v[it].x + v[it].y) + (v[it].z + v[it].w);
                m = fmaxf(m, fmaxf(fmaxf(v[it].x, v[it].y),
                                   fmaxf(v[it].z, v[it].w)));
            }
        }
#pragma unroll
        for (int o = 16; o; o >>= 1) {
            s += __shfl_xor_sync(0xffffffffu, s, o);
            m = fmaxf(m, __shfl_xor_sync(0xffffffffu, m, o));
        }
        if (lane == 0) { ss[wrp] = s; sm2[wrp] = m; }
        __syncthreads();
        if (tid == 0) {
            float ts = 0.0f, tm = -3.4e38f;
#pragma unroll
            for (int i = 0; i < 16; i++) { ts += ss[i]; tm = fmaxf(tm, sm2[i]); }
            g_psum[item] = ts;
            g_pmax[item] = tm;
        }
        __syncthreads();
    }

    grid_barrier();

    // ---- Phase B: channel MLP on blocks 0,1 (batch = blockIdx.x) ----------
    if (blockIdx.x < 2) {
        const int b = blockIdx.x;

        if (tid < 256) {       // phase 0+1: pooled value -> silu + bases
            const int src = tid >> 7, c = tid & 127;
            const int pair = b * C_SZ + c;
            float v;
            if (src == 0) {
                float ts = 0.0f;
#pragma unroll
                for (int k = 0; k < NCHUNK; k++) ts += __ldcg(&g_psum[pair * NCHUNK + k]);
                v = ts * (1.0f / (float)S_SZ);
            } else {
                float tm = -3.4e38f;
#pragma unroll
                for (int k = 0; k < NCHUNK; k++) tm = fmaxf(tm, __ldcg(&g_pmax[pair * NCHUNK + k]));
                v = tm;
            }
            s_silu[tid] = siluf(v);
            bspline8(v, s_bas[tid]);
        }
        __syncthreads();

        if (tid < 256) {       // phase 2: 16 tasks (src x r) x 16 lanes
            const int task = tid >> 4, j = tid & 15;
            const int src = task >> 3, r = task & 7;
            const int base = src * 128;
            float acc = 0.0f;
#pragma unroll
            for (int ii = 0; ii < 8; ii++) {
                const int i = j + ii * 16;
                const int q = base + i;
                acc += s_silu[q] * ck1b[r * C_SZ + i];
                const float4* sw = (const float4*)(ck1s + (r * C_SZ + i) * GBASES);
                const float4 a0 = sw[0], a1 = sw[1];
                acc += s_bas[q][0] * a0.x + s_bas[q][1] * a0.y
                     + s_bas[q][2] * a0.z + s_bas[q][3] * a0.w
                     + s_bas[q][4] * a1.x + s_bas[q][5] * a1.y
                     + s_bas[q][6] * a1.z + s_bas[q][7] * a1.w;
            }
#pragma unroll
            for (int o = 8; o; o >>= 1) acc += __shfl_xor_sync(0xffffffffu, acc, o);
            if (j == 0) {
                const float hv = fmaxf(acc, 0.0f);
                s_h1silu[task] = siluf(hv);
                bspline8(hv, s_h1bas[task]);
            }
        }
        __syncthreads();

        if (tid < 256) {       // phase 3: layer 2
            const int src = tid >> 7, c = tid & 127;
            float acc = 0.0f;
#pragma unroll
            for (int r = 0; r < 8; r++) {
                const int hq = src * 8 + r;
                acc += s_h1silu[hq] * ck2b[c * 8 + r];
                const float4* sw = (const float4*)(ck2s + (c * 8 + r) * GBASES);
                const float4 a0 = sw[0], a1 = sw[1];
                acc += s_h1bas[hq][0] * a0.x + s_h1bas[hq][1] * a0.y
                     + s_h1bas[hq][2] * a0.z + s_h1bas[hq][3] * a0.w
                     + s_h1bas[hq][4] * a1.x + s_h1bas[hq][5] * a1.y
                     + s_h1bas[hq][6] * a1.z + s_h1bas[hq][7] * a1.w;
            }
            s_out[tid] = acc;
        }
        __syncthreads();

        if (tid < 128) {       // phase 4
            const float a = sigmoidf_(s_out[tid] + s_out[128 + tid]);
            g_att[b * C_SZ + tid] = a;
            g_wc[b * C_SZ + tid]  = a * convw[tid];
        }
    }

    grid_barrier();

    // ---- Phase C: fused spatial pass, strided tiles -----------------------
    if (tid < NPAIR) {         // stage attention once per block (L2-fresh)
        att_s[tid] = __ldcg(&g_att[tid]);
        wc_s[tid]  = __ldcg(&g_wc[tid]);
    }
    __syncthreads();

    const float kb = skb[0];
    float swt[GBASES];
#pragma unroll
    for (int g = 0; g < GBASES; g++) swt[g] = sks[g];

    const int cbase = wrp * 8;
    for (unsigned t = blockIdx.x; t < NTILES; t += nb) {
        const int b    = t >> 11;
        const int tile = t & 2047;
        const size_t sbase4 = (size_t)tile * TILE_V4;

        float4 va[8];
        float4 ws = make_float4(0.f, 0.f, 0.f, 0.f);
#pragma unroll
        for (int k = 0; k < 8; k++) {
            const int pair = b * C_SZ + cbase + k;
            const float4 v = __ldcs(&xp[((size_t)pair << 16) + sbase4 + (size_t)lane]);
            const float a  = att_s[pair];
            const float wc = wc_s[pair];
            va[k] = make_float4(v.x * a, v.y * a, v.z * a, v.w * a);
            ws.x += v.x * wc; ws.y += v.y * wc; ws.z += v.z * wc; ws.w += v.w * wc;
        }
        wred[wrp][lane] = ws;
        __syncthreads();

        if (tid < TILE_VOX) {
            const int l4 = tid >> 2, j = tid & 3;
            float y = 0.0f;
#pragma unroll
            for (int p = 0; p < 16; p++) y += ((const float*)&wred[p][l4])[j];

            float bas[GBASES];
            bspline8(y, bas);
            float acc = siluf(y) * kb;
#pragma unroll
            for (int g = 0; g < GBASES; g++) acc += bas[g] * swt[g];
            satts[tid] = sigmoidf_(acc);
        }
        __syncthreads();

        const float4 sa = ((const float4*)satts)[lane];
#pragma unroll
        for (int k = 0; k < 8; k++) {
            const int pair = b * C_SZ + cbase + k;
            __stcs(&op[((size_t)pair << 16) + sbase4 + (size_t)lane],
                   make_float4(va[k].x * sa.x, va[k].y * sa.y,
                               va[k].z * sa.z, va[k].w * sa.w));
        }
    }
}

// ---------------------------------------------------------------------------
// Launch — grid sized to guaranteed co-residency (occupancy x numSMs), so the
// in-kernel grid barrier cannot deadlock. Host queries are capture-safe.
// ---------------------------------------------------------------------------
extern "C" void kernel_launch(void* const* d_in, const int* in_sizes, int n_in,
                              void* d_out, int out_size) {
    const float* x     = (const float*)d_in[0];
    const float* ck1b  = (const float*)d_in[1];
    const float* ck1s  = (const float*)d_in[2];
    const float* ck2b  = (const float*)d_in[3];
    const float* ck2s  = (const float*)d_in[4];
    const float* convw = (const float*)d_in[5];
    const float* skb   = (const float*)d_in[6];
    const float* sks   = (const float*)d_in[7];
    float* out = (float*)d_out;

    int dev = 0, nsm = 0, occ = 0;
    cudaGetDevice(&dev);
    cudaDeviceGetAttribute(&nsm, cudaDevAttrMultiProcessorCount, dev);
    cudaOccupancyMaxActiveBlocksPerMultiprocessor(&occ, mega_kernel, 512, 0);
    if (occ < 1) occ = 1;
    unsigned nb = (unsigned)(nsm * occ);
    if (nb > POOL_ITEMS) nb = POOL_ITEMS;

    mega_kernel<<<nb, 512>>>(x, ck1b, ck1s, ck2b, ck2s, convw, skb, sks, out);
}